// round 5
// baseline (speedup 1.0000x reference)
#include <cuda_runtime.h>
#include <cstdint>

typedef unsigned long long u64;

#define Bb   512
#define Tt   512
#define Ff   32
#define Hh   128
#define Ee   64
#define BT   4
#define NB   (Bb/BT)

// layer 1: 1024 thr = 128 colgroups(4 cols) x 8 K-parts, K=160 -> 20/thread
#define KP1  20
// layer 2: 512 thr = 64 colgroups(4 cols) x 8 K-parts, K=192 -> 24/thread
#define KP2  24

#define A2_1_BYTES (160*4*8)                 // 5120
#define PF_1_BYTES (8*4*512*4)               // 65536
#define SM1_BYTES  (A2_1_BYTES + PF_1_BYTES) // 70656

#define A2_2_BYTES (192*4*8)                 // 6144
#define PF_2_BYTES (8*4*256*4)               // 32768
#define SM2_BYTES  (A2_2_BYTES + PF_2_BYTES) // 38912

__device__ float g_seq1[(size_t)Tt*Bb*Hh];   // [T][B][H]

__device__ __forceinline__ u64 ffma2(u64 a, u64 b, u64 c) {
    u64 d;
    asm("fma.rn.f32x2 %0, %1, %2, %3;" : "=l"(d) : "l"(a), "l"(b), "l"(c));
    return d;
}
__device__ __forceinline__ u64 pk2(float x, float y) {
    u64 r;
    asm("mov.b64 %0, {%1, %2};" : "=l"(r) : "f"(x), "f"(y));
    return r;
}
__device__ __forceinline__ float sigm(float z) {
    return __fdividef(1.0f, 1.0f + __expf(-z));
}
__device__ __forceinline__ float tanh_(float z) {
    float e = __expf(2.0f*z);
    return 1.0f - __fdividef(2.0f, e + 1.0f);
}

// ---------------------------------------------------------------------------
// Layer 1. 128 blocks x 1024 threads. thread = (colgroup g: 4 cols, K-part).
// All weights in registers (40 u64). Split-K8 partials reduced in epilogue.
// ---------------------------------------------------------------------------
__global__ void __launch_bounds__(1024, 1)
lstm1_kernel(const float* __restrict__ x,
             const float* __restrict__ Wih, const float* __restrict__ Whh,
             const float* __restrict__ bih, const float* __restrict__ bhh)
{
    extern __shared__ char smraw[];
    u64*   a2 = (u64*)smraw;                       // [160][4] duplicated acts
    float* pf = (float*)(smraw + A2_1_BYTES);      // [8][4][512] partials

    const int tid  = threadIdx.x;
    const int g    = tid & 127;          // col group
    const int part = tid >> 7;           // K part 0..7
    const int c0   = g * 4;
    const int r0   = blockIdx.x * BT;
    const int k0   = part * KP1;

    // register weights: pair A = cols c0,c0+1 ; pair B = cols c0+2,c0+3
    u64 wA[KP1], wB[KP1];
#pragma unroll
    for (int i = 0; i < KP1; i++) {
        int k = k0 + i;
        float a0, a1, b0, b1;
        if (k < Hh) {
            a0 = Whh[(c0+0)*Hh + k]; a1 = Whh[(c0+1)*Hh + k];
            b0 = Whh[(c0+2)*Hh + k]; b1 = Whh[(c0+3)*Hh + k];
        } else {
            a0 = Wih[(c0+0)*Ff + k - Hh]; a1 = Wih[(c0+1)*Ff + k - Hh];
            b0 = Wih[(c0+2)*Ff + k - Hh]; b1 = Wih[(c0+3)*Ff + k - Hh];
        }
        wA[i] = pk2(a0, a1);
        wB[i] = pk2(b0, b1);
    }

    // epilogue cell (hidden j, batch b) for tid<512; biases in regs
    const int ej = tid & 127, eb = (tid >> 7) & 3;
    float bi_ = 0.f, bf_ = 0.f, bg_ = 0.f, bo_ = 0.f;
    if (tid < 512) {
        bi_ = bih[       ej] + bhh[       ej];
        bf_ = bih[Hh   + ej] + bhh[Hh   + ej];
        bg_ = bih[2*Hh + ej] + bhh[2*Hh + ej];
        bo_ = bih[3*Hh + ej] + bhh[3*Hh + ej];
    }

    // zero h region of a2
    for (int i = tid; i < Hh*BT; i += 1024) a2[i] = 0ULL;

    // x loaders: threads 0..127 own (feature xf, batch xb)
    const int xf = tid & 31, xb = (tid >> 5) & 3;
    float xc = 0.0f;
    if (tid < Hh) {
        float x0 = x[((size_t)(r0 + xb)*Tt + 0)*Ff + xf];
        a2[(Hh + xf)*4 + xb] = pk2(x0, x0);
        xc = x[((size_t)(r0 + xb)*Tt + 1)*Ff + xf];
    }
    float cst = 0.0f;
    __syncthreads();

    const ulonglong2* a2v = (const ulonglong2*)(a2 + (size_t)k0*4);
    float* pfp = pf + part*4*512;

    for (int t = 0; t < Tt; t++) {
        u64 aA0=0, aA1=0, aA2=0, aA3=0, aB0=0, aB1=0, aB2=0, aB3=0;
#pragma unroll
        for (int i = 0; i < KP1; i++) {
            ulonglong2 vA = a2v[2*i];       // b0,b1 (each duplicated pair)
            ulonglong2 vB = a2v[2*i + 1];   // b2,b3
            aA0 = ffma2(wA[i], vA.x, aA0);
            aA1 = ffma2(wA[i], vA.y, aA1);
            aA2 = ffma2(wA[i], vB.x, aA2);
            aA3 = ffma2(wA[i], vB.y, aA3);
            aB0 = ffma2(wB[i], vA.x, aB0);
            aB1 = ffma2(wB[i], vA.y, aB1);
            aB2 = ffma2(wB[i], vB.x, aB2);
            aB3 = ffma2(wB[i], vB.y, aB3);
        }
        // partials: pf[part][b][col]; u64 store covers cols (c0,c0+1)/(c0+2,c0+3)
        *(u64*)(pfp + 0*512 + c0    ) = aA0;
        *(u64*)(pfp + 1*512 + c0    ) = aA1;
        *(u64*)(pfp + 2*512 + c0    ) = aA2;
        *(u64*)(pfp + 3*512 + c0    ) = aA3;
        *(u64*)(pfp + 0*512 + c0 + 2) = aB0;
        *(u64*)(pfp + 1*512 + c0 + 2) = aB1;
        *(u64*)(pfp + 2*512 + c0 + 2) = aB2;
        *(u64*)(pfp + 3*512 + c0 + 2) = aB3;
        __syncthreads();

        if (tid < 512) {
            float zi = bi_, zf = bf_, zg = bg_, zo = bo_;
            const float* pb = pf + eb*512;
#pragma unroll
            for (int p = 0; p < 8; p++) {
                const float* q = pb + p*4*512;
                zi += q[         ej];
                zf += q[Hh    +  ej];
                zg += q[2*Hh  +  ej];
                zo += q[3*Hh  +  ej];
            }
            cst = sigm(zf)*cst + sigm(zi)*tanh_(zg);
            float h = sigm(zo)*tanh_(cst);
            a2[ej*4 + eb] = pk2(h, h);
            g_seq1[((size_t)t*Bb + r0 + eb)*Hh + ej] = h;
            if (tid < Hh) {
                a2[(Hh + xf)*4 + xb] = pk2(xc, xc);   // x for step t+1
                xc = (t + 2 < Tt) ? x[((size_t)(r0 + xb)*Tt + t + 2)*Ff + xf] : 0.0f;
            }
        }
        __syncthreads();
    }
}

// ---------------------------------------------------------------------------
// Layer 2. 128 blocks x 512 threads. thread = (colgroup: 4 cols, K-part of 8).
// ---------------------------------------------------------------------------
__global__ void __launch_bounds__(512, 1)
lstm2_kernel(const float* __restrict__ Wih, const float* __restrict__ Whh,
             const float* __restrict__ bih, const float* __restrict__ bhh,
             float* __restrict__ out)
{
    extern __shared__ char smraw[];
    u64*   a2 = (u64*)smraw;                       // [192][4]
    float* pf = (float*)(smraw + A2_2_BYTES);      // [8][4][256]

    const int tid  = threadIdx.x;
    const int g    = tid & 63;
    const int part = tid >> 6;
    const int c0   = g * 4;
    const int r0   = blockIdx.x * BT;
    const int k0   = part * KP2;

    u64 wA[KP2], wB[KP2];
#pragma unroll
    for (int i = 0; i < KP2; i++) {
        int k = k0 + i;
        float a0, a1, b0, b1;
        if (k < Hh) {
            a0 = Wih[(c0+0)*Hh + k]; a1 = Wih[(c0+1)*Hh + k];
            b0 = Wih[(c0+2)*Hh + k]; b1 = Wih[(c0+3)*Hh + k];
        } else {
            a0 = Whh[(c0+0)*Ee + k - Hh]; a1 = Whh[(c0+1)*Ee + k - Hh];
            b0 = Whh[(c0+2)*Ee + k - Hh]; b1 = Whh[(c0+3)*Ee + k - Hh];
        }
        wA[i] = pk2(a0, a1);
        wB[i] = pk2(b0, b1);
    }

    const int ej = tid & 63, eb = (tid >> 6) & 3;   // cell for tid<256
    float bi_ = 0.f, bf_ = 0.f, bg_ = 0.f, bo_ = 0.f;
    if (tid < 256) {
        bi_ = bih[       ej] + bhh[       ej];
        bf_ = bih[Ee   + ej] + bhh[Ee   + ej];
        bg_ = bih[2*Ee + ej] + bhh[2*Ee + ej];
        bo_ = bih[3*Ee + ej] + bhh[3*Ee + ej];
    }

    // zero h2 region
    for (int i = tid; i < Ee*BT; i += 512) a2[Hh*4 + i] = 0ULL;

    // h1 loaders: 512 threads = (kk 0..127, bb 0..3)
    const int kk = tid & 127, bb = tid >> 7;
    {
        float v0 = g_seq1[((size_t)0*Bb + r0 + bb)*Hh + kk];
        a2[kk*4 + bb] = pk2(v0, v0);
    }
    float cst = 0.0f, hout = 0.0f;
    __syncthreads();

    const ulonglong2* a2v = (const ulonglong2*)(a2 + (size_t)k0*4);
    float* pfp = pf + part*4*256;

    for (int t = 0; t < Tt; t++) {
        float vn = (t + 1 < Tt) ? g_seq1[((size_t)(t+1)*Bb + r0 + bb)*Hh + kk] : 0.0f;

        u64 aA0=0, aA1=0, aA2=0, aA3=0, aB0=0, aB1=0, aB2=0, aB3=0;
#pragma unroll
        for (int i = 0; i < KP2; i++) {
            ulonglong2 vA = a2v[2*i];
            ulonglong2 vB = a2v[2*i + 1];
            aA0 = ffma2(wA[i], vA.x, aA0);
            aA1 = ffma2(wA[i], vA.y, aA1);
            aA2 = ffma2(wA[i], vB.x, aA2);
            aA3 = ffma2(wA[i], vB.y, aA3);
            aB0 = ffma2(wB[i], vA.x, aB0);
            aB1 = ffma2(wB[i], vA.y, aB1);
            aB2 = ffma2(wB[i], vB.x, aB2);
            aB3 = ffma2(wB[i], vB.y, aB3);
        }
        *(u64*)(pfp + 0*256 + c0    ) = aA0;
        *(u64*)(pfp + 1*256 + c0    ) = aA1;
        *(u64*)(pfp + 2*256 + c0    ) = aA2;
        *(u64*)(pfp + 3*256 + c0    ) = aA3;
        *(u64*)(pfp + 0*256 + c0 + 2) = aB0;
        *(u64*)(pfp + 1*256 + c0 + 2) = aB1;
        *(u64*)(pfp + 2*256 + c0 + 2) = aB2;
        *(u64*)(pfp + 3*256 + c0 + 2) = aB3;
        __syncthreads();

        if (tid < 256) {
            float zi = bi_, zf = bf_, zg = bg_, zo = bo_;
            const float* pb = pf + eb*256;
#pragma unroll
            for (int p = 0; p < 8; p++) {
                const float* q = pb + p*4*256;
                zi += q[        ej];
                zf += q[Ee   +  ej];
                zg += q[2*Ee +  ej];
                zo += q[3*Ee +  ej];
            }
            cst = sigm(zf)*cst + sigm(zi)*tanh_(zg);
            hout = sigm(zo)*tanh_(cst);
            a2[(Hh + ej)*4 + eb] = pk2(hout, hout);
        }
        a2[kk*4 + bb] = pk2(vn, vn);   // h1 for step t+1 (disjoint from h2 region)
        __syncthreads();
    }

    if (tid < 256) out[(size_t)(r0 + eb)*Ee + ej] = hout;
}

extern "C" void kernel_launch(void* const* d_in, const int* in_sizes, int n_in,
                              void* d_out, int out_size)
{
    const float* x    = (const float*)d_in[0];
    const float* Wih1 = (const float*)d_in[1];
    const float* Whh1 = (const float*)d_in[2];
    const float* bih1 = (const float*)d_in[3];
    const float* bhh1 = (const float*)d_in[4];
    const float* Wih2 = (const float*)d_in[5];
    const float* Whh2 = (const float*)d_in[6];
    const float* bih2 = (const float*)d_in[7];
    const float* bhh2 = (const float*)d_in[8];
    float* out = (float*)d_out;

    cudaFuncSetAttribute(lstm1_kernel, cudaFuncAttributeMaxDynamicSharedMemorySize, SM1_BYTES);
    cudaFuncSetAttribute(lstm2_kernel, cudaFuncAttributeMaxDynamicSharedMemorySize, SM2_BYTES);

    lstm1_kernel<<<NB, 1024, SM1_BYTES>>>(x, Wih1, Whh1, bih1, bhh1);
    lstm2_kernel<<<NB, 512, SM2_BYTES>>>(Wih2, Whh2, bih2, bhh2, out);
}

// round 7
// speedup vs baseline: 2.5579x; 2.5579x over previous
#include <cuda_runtime.h>
#include <cuda_fp16.h>
#include <cstdint>

#define Bb 512
#define Tt 512
#define Ff 32
#define Hh 128
#define Ee 64
#define KPAD 200

__device__ uint32_t g_seq1[(size_t)Tt*Bb*Hh];   // layer-1 h packed (hi | lo<<16) fp16

// ---------------- helpers ----------------
__device__ __forceinline__ uint32_t smem_u32(const void* p) {
    uint32_t a;
    asm("{ .reg .u64 t; cvta.to.shared.u64 t, %1; cvt.u32.u64 %0, t; }" : "=r"(a) : "l"(p));
    return a;
}
__device__ __forceinline__ void mma16816(float* d, const uint32_t* a, uint32_t b0, uint32_t b1) {
    asm("mma.sync.aligned.m16n8k16.row.col.f32.f16.f16.f32 "
        "{%0,%1,%2,%3}, {%4,%5,%6,%7}, {%8,%9}, {%0,%1,%2,%3};"
        : "+f"(d[0]), "+f"(d[1]), "+f"(d[2]), "+f"(d[3])
        : "r"(a[0]), "r"(a[1]), "r"(a[2]), "r"(a[3]), "r"(b0), "r"(b1));
}
__device__ __forceinline__ void splith(float v, __half& hi, __half& lo) {
    hi = __float2half_rn(v);
    lo = __float2half_rn(v - __half2float(hi));
}
__device__ __forceinline__ uint32_t pkh(__half a, __half b) {
    return (uint32_t)__half_as_ushort(a) | ((uint32_t)__half_as_ushort(b) << 16);
}
__device__ __forceinline__ void mbar_init(void* m, uint32_t cnt) {
    asm volatile("mbarrier.init.shared.b64 [%0], %1;" :: "r"(smem_u32(m)), "r"(cnt) : "memory");
}
__device__ __forceinline__ void mbar_wait(void* m, uint32_t parity) {
    uint32_t a = smem_u32(m), done;
    do {
        asm volatile("{\n\t.reg .pred p;\n\t"
            "mbarrier.try_wait.parity.acquire.cluster.shared::cta.b64 p, [%1], %2, 0x989680;\n\t"
            "selp.b32 %0, 1, 0, p;\n\t}" : "=r"(done) : "r"(a), "r"(parity) : "memory");
    } while (!done);
}
__device__ __forceinline__ void remote_arrive(void* m, uint32_t peer) {
    asm volatile("{\n\t.reg .b32 ra;\n\tmapa.shared::cluster.u32 ra, %0, %1;\n\t"
        "mbarrier.arrive.release.cluster.shared::cluster.b64 _, [ra];\n\t}"
        :: "r"(smem_u32(m)), "r"(peer) : "memory");
}
__device__ __forceinline__ void st_peer16(const void* p, uint32_t peer, uint16_t v) {
    asm volatile("{\n\t.reg .b32 ra;\n\tmapa.shared::cluster.u32 ra, %0, %1;\n\t"
        "st.shared::cluster.b16 [ra], %2;\n\t}"
        :: "r"(smem_u32(p)), "r"(peer), "h"(v) : "memory");
}
#define CLU_SYNC() do { asm volatile("barrier.cluster.arrive.aligned;" ::: "memory"); \
                        asm volatile("barrier.cluster.wait.aligned;" ::: "memory"); } while (0)

__device__ __forceinline__ float sigm(float z) { return __fdividef(1.0f, 1.0f + __expf(-z)); }
__device__ __forceinline__ float tanh_(float z) {
    float e = __expf(2.0f * z);
    return 1.0f - __fdividef(2.0f, e + 1.0f);
}

// ---------------------------------------------------------------------------
// Layer 1: 64 clusters x 2 CTAs x 512 threads. Cluster = 8 batch rows.
// CTA owns 256 gate rows (4 gates x 64 units, units U0..U0+63).
// Local gate row r: gate = r>>6, unit = U0 + (r&63). K: 0..127 h, 128..159 x.
// ---------------------------------------------------------------------------
__global__ void __launch_bounds__(512, 1) __cluster_dims__(2, 1, 1)
lstm1_mma(const float* __restrict__ x,
          const float* __restrict__ Wih, const float* __restrict__ Whh,
          const float* __restrict__ bih, const float* __restrict__ bhh)
{
    __shared__ __half Bhi[2][8][KPAD];
    __shared__ __half Blo[2][8][KPAD];
    __shared__ float pf[256 * 9];
    __shared__ alignas(8) unsigned long long mbar[2];

    const int tid = threadIdx.x;
    uint32_t rank;
    asm("mov.u32 %0, %%cluster_ctarank;" : "=r"(rank));
    const int r0 = (blockIdx.x >> 1) * 8;
    const int U0 = (int)rank * 64;
    const int lane = tid & 31, warp = tid >> 5;
    const int tg = lane & 3, gid = lane >> 2;
    const int rbase = warp * 16;

    // zero activation buffers (h starts at 0; pad region stays 0)
    for (int i = tid; i < 2 * 8 * KPAD; i += 512) {
        (&Bhi[0][0][0])[i] = __ushort_as_half(0);
        (&Blo[0][0][0])[i] = __ushort_as_half(0);
    }

    // register-resident weight fragments (hi + lo), 10 k-frags
    uint32_t Ahi[10][4], Alo[10][4];
#pragma unroll
    for (int kf = 0; kf < 10; kf++) {
        int k0 = kf * 16 + tg * 2;
#pragma unroll
        for (int q = 0; q < 4; q++) {
            int rr = rbase + gid + (q & 1) * 8;
            int kk = k0 + (q >> 1) * 8;
            int R = (rr >> 6) * Hh + U0 + (rr & 63);
            float w0 = (kk < Hh) ? Whh[R * Hh + kk] : Wih[R * Ff + (kk - Hh)];
            float w1 = (kk + 1 < Hh) ? Whh[R * Hh + kk + 1] : Wih[R * Ff + (kk + 1 - Hh)];
            __half h0, l0, h1, l1;
            splith(w0, h0, l0);
            splith(w1, h1, l1);
            Ahi[kf][q] = pkh(h0, h1);
            Alo[kf][q] = pkh(l0, l1);
        }
    }

    // cell assignment: unit j (local), batch b
    const int j = tid & 63, b = tid >> 6;
    const int u = U0 + j;
    const float bi_ = bih[u] + bhh[u];
    const float bf_ = bih[Hh + u] + bhh[Hh + u];
    const float bg_ = bih[2 * Hh + u] + bhh[2 * Hh + u];
    const float bo_ = bih[3 * Hh + u] + bhh[3 * Hh + u];

    if (tid == 0) { mbar_init(&mbar[0], 512); mbar_init(&mbar[1], 512); }
    __syncthreads();

    // x loaders: tid<256, (batch xb, feature xf); write x(t=0) into buf 0
    const int xb = tid >> 5, xf = tid & 31;
    float xn = 0.0f;
    if (tid < 256) {
        float x0 = x[((size_t)(r0 + xb) * Tt + 0) * Ff + xf];
        __half xh, xl;
        splith(x0, xh, xl);
        Bhi[0][xb][Hh + xf] = xh;
        Blo[0][xb][Hh + xf] = xl;
        xn = x[((size_t)(r0 + xb) * Tt + 1) * Ff + xf];
    }
    __syncthreads();
    CLU_SYNC();   // mbar init + initial buffers visible cluster-wide

    float cst = 0.0f;
    int ph0 = 0, ph1 = 0;
    const int boffw = gid * KPAD + tg * 2;

    for (int t = 0; t < Tt; t++) {
        const int cur = t & 1;
        if (t > 0) {
            if (cur == 0) { mbar_wait(&mbar[0], (uint32_t)ph0); ph0 ^= 1; }
            else          { mbar_wait(&mbar[1], (uint32_t)ph1); ph1 ^= 1; }
        }

        float d[4] = {0.f, 0.f, 0.f, 0.f};
        const __half* bh = &Bhi[cur][0][0];
        const __half* bl = &Blo[cur][0][0];
#pragma unroll
        for (int kf = 0; kf < 10; kf++) {
            uint32_t b0 = *(const uint32_t*)(bh + boffw + kf * 16);
            uint32_t b1 = *(const uint32_t*)(bh + boffw + kf * 16 + 8);
            uint32_t c0 = *(const uint32_t*)(bl + boffw + kf * 16);
            uint32_t c1 = *(const uint32_t*)(bl + boffw + kf * 16 + 8);
            mma16816(d, Ahi[kf], b0, b1);
            mma16816(d, Alo[kf], b0, b1);
            mma16816(d, Ahi[kf], c0, c1);
        }
        pf[(rbase + gid) * 9 + tg * 2]         = d[0];
        pf[(rbase + gid) * 9 + tg * 2 + 1]     = d[1];
        pf[(rbase + gid + 8) * 9 + tg * 2]     = d[2];
        pf[(rbase + gid + 8) * 9 + tg * 2 + 1] = d[3];
        __syncthreads();

        float zi = pf[j * 9 + b] + bi_;
        float zf = pf[(64 + j) * 9 + b] + bf_;
        float zg = pf[(128 + j) * 9 + b] + bg_;
        float zo = pf[(192 + j) * 9 + b] + bo_;
        cst = sigm(zf) * cst + sigm(zi) * tanh_(zg);
        float h = sigm(zo) * tanh_(cst);
        __half hh, hl;
        splith(h, hh, hl);
        g_seq1[((size_t)t * Bb + r0 + b) * Hh + u] = pkh(hh, hl);

        if (t + 1 < Tt) {
            const int nb = cur ^ 1;
            Bhi[nb][b][u] = hh;
            Blo[nb][b][u] = hl;
            st_peer16(&Bhi[nb][b][u], rank ^ 1u, __half_as_ushort(hh));
            st_peer16(&Blo[nb][b][u], rank ^ 1u, __half_as_ushort(hl));
            if (tid < 256) {
                __half xh, xl;
                splith(xn, xh, xl);
                Bhi[nb][xb][Hh + xf] = xh;
                Blo[nb][xb][Hh + xf] = xl;
                xn = (t + 2 < Tt) ? x[((size_t)(r0 + xb) * Tt + t + 2) * Ff + xf] : 0.0f;
            }
            remote_arrive(&mbar[nb], rank ^ 1u);   // after remote stores (release)
        }
        __syncthreads();
    }
    CLU_SYNC();   // no CTA exits while peer stores may be in flight
}

// ---------------------------------------------------------------------------
// Layer 2: 64 blocks x 512 threads, no cluster. M=256 gate rows, K=192
// (0..127 h1 from g_seq1, 128..191 h2).
// ---------------------------------------------------------------------------
__global__ void __launch_bounds__(512, 1)
lstm2_mma(const float* __restrict__ Wih, const float* __restrict__ Whh,
          const float* __restrict__ bih, const float* __restrict__ bhh,
          float* __restrict__ out)
{
    __shared__ __half Bhi[2][8][KPAD];
    __shared__ __half Blo[2][8][KPAD];
    __shared__ float pf[256 * 9];

    const int tid = threadIdx.x;
    const int r0 = blockIdx.x * 8;
    const int lane = tid & 31, warp = tid >> 5;
    const int tg = lane & 3, gid = lane >> 2;
    const int rbase = warp * 16;

    for (int i = tid; i < 2 * 8 * KPAD; i += 512) {
        (&Bhi[0][0][0])[i] = __ushort_as_half(0);
        (&Blo[0][0][0])[i] = __ushort_as_half(0);
    }

    uint32_t Ahi[12][4], Alo[12][4];
#pragma unroll
    for (int kf = 0; kf < 12; kf++) {
        int k0 = kf * 16 + tg * 2;
#pragma unroll
        for (int q = 0; q < 4; q++) {
            int rr = rbase + gid + (q & 1) * 8;
            int kk = k0 + (q >> 1) * 8;
            int R = (rr >> 6) * Ee + (rr & 63);
            float w0 = (kk < Hh) ? Wih[R * Hh + kk] : Whh[R * Ee + (kk - Hh)];
            float w1 = (kk + 1 < Hh) ? Wih[R * Hh + kk + 1] : Whh[R * Ee + (kk + 1 - Hh)];
            __half h0, l0, h1, l1;
            splith(w0, h0, l0);
            splith(w1, h1, l1);
            Ahi[kf][q] = pkh(h0, h1);
            Alo[kf][q] = pkh(l0, l1);
        }
    }

    const int j = tid & 63, b = tid >> 6;
    const float bi_ = bih[j] + bhh[j];
    const float bf_ = bih[Ee + j] + bhh[Ee + j];
    const float bg_ = bih[2 * Ee + j] + bhh[2 * Ee + j];
    const float bo_ = bih[3 * Ee + j] + bhh[3 * Ee + j];

    // h1 loaders: thread -> (k=lk, batches lb and lb+4)
    const int lk = tid & 127, lb = tid >> 7;
    __syncthreads();   // B zero complete
    uint32_t p0 = g_seq1[((size_t)0 * Bb + r0 + lb) * Hh + lk];
    uint32_t p1 = g_seq1[((size_t)0 * Bb + r0 + lb + 4) * Hh + lk];
    Bhi[0][lb][lk]     = __ushort_as_half((uint16_t)(p0 & 0xFFFF));
    Blo[0][lb][lk]     = __ushort_as_half((uint16_t)(p0 >> 16));
    Bhi[0][lb + 4][lk] = __ushort_as_half((uint16_t)(p1 & 0xFFFF));
    Blo[0][lb + 4][lk] = __ushort_as_half((uint16_t)(p1 >> 16));
    p0 = g_seq1[((size_t)1 * Bb + r0 + lb) * Hh + lk];
    p1 = g_seq1[((size_t)1 * Bb + r0 + lb + 4) * Hh + lk];
    __syncthreads();

    float cst = 0.0f, hlast = 0.0f;
    const int boffw = gid * KPAD + tg * 2;

    for (int t = 0; t < Tt; t++) {
        const int cur = t & 1;
        float d[4] = {0.f, 0.f, 0.f, 0.f};
        const __half* bh = &Bhi[cur][0][0];
        const __half* bl = &Blo[cur][0][0];
#pragma unroll
        for (int kf = 0; kf < 12; kf++) {
            uint32_t b0 = *(const uint32_t*)(bh + boffw + kf * 16);
            uint32_t b1 = *(const uint32_t*)(bh + boffw + kf * 16 + 8);
            uint32_t c0 = *(const uint32_t*)(bl + boffw + kf * 16);
            uint32_t c1 = *(const uint32_t*)(bl + boffw + kf * 16 + 8);
            mma16816(d, Ahi[kf], b0, b1);
            mma16816(d, Alo[kf], b0, b1);
            mma16816(d, Ahi[kf], c0, c1);
        }
        pf[(rbase + gid) * 9 + tg * 2]         = d[0];
        pf[(rbase + gid) * 9 + tg * 2 + 1]     = d[1];
        pf[(rbase + gid + 8) * 9 + tg * 2]     = d[2];
        pf[(rbase + gid + 8) * 9 + tg * 2 + 1] = d[3];
        __syncthreads();

        float zi = pf[j * 9 + b] + bi_;
        float zf = pf[(64 + j) * 9 + b] + bf_;
        float zg = pf[(128 + j) * 9 + b] + bg_;
        float zo = pf[(192 + j) * 9 + b] + bo_;
        cst = sigm(zf) * cst + sigm(zi) * tanh_(zg);
        hlast = sigm(zo) * tanh_(cst);

        if (t + 1 < Tt) {
            const int nb = cur ^ 1;
            __half hh, hl;
            splith(hlast, hh, hl);
            Bhi[nb][b][Hh + j] = hh;
            Blo[nb][b][Hh + j] = hl;
            // h1 for step t+1
            Bhi[nb][lb][lk]     = __ushort_as_half((uint16_t)(p0 & 0xFFFF));
            Blo[nb][lb][lk]     = __ushort_as_half((uint16_t)(p0 >> 16));
            Bhi[nb][lb + 4][lk] = __ushort_as_half((uint16_t)(p1 & 0xFFFF));
            Blo[nb][lb + 4][lk] = __ushort_as_half((uint16_t)(p1 >> 16));
            if (t + 2 < Tt) {
                p0 = g_seq1[((size_t)(t + 2) * Bb + r0 + lb) * Hh + lk];
                p1 = g_seq1[((size_t)(t + 2) * Bb + r0 + lb + 4) * Hh + lk];
            }
        }
        __syncthreads();
    }
    out[(size_t)(r0 + b) * Ee + j] = hlast;
}

extern "C" void kernel_launch(void* const* d_in, const int* in_sizes, int n_in,
                              void* d_out, int out_size)
{
    const float* x    = (const float*)d_in[0];
    const float* Wih1 = (const float*)d_in[1];
    const float* Whh1 = (const float*)d_in[2];
    const float* bih1 = (const float*)d_in[3];
    const float* bhh1 = (const float*)d_in[4];
    const float* Wih2 = (const float*)d_in[5];
    const float* Whh2 = (const float*)d_in[6];
    const float* bih2 = (const float*)d_in[7];
    const float* bhh2 = (const float*)d_in[8];
    float* out = (float*)d_out;

    lstm1_mma<<<128, 512>>>(x, Wih1, Whh1, bih1, bhh1);
    lstm2_mma<<<64, 512>>>(Wih2, Whh2, bih2, bhh2, out);
}